// round 15
// baseline (speedup 1.0000x reference)
#include <cuda_runtime.h>
#include <cuda_fp16.h>
#include <cstdint>

#define BB     8
#define TT     4096
#define DM     1024
#define DS     16
#define MM     (BB * TT)
#define LN_EPS 1e-5f

// ------------------------- scratch (static, no alloc) ----------------------
__device__ __half  g_gph [(size_t)MM * DM];      // gate_pre fp16 (64 MB)
__device__ __half  g_xb  [(size_t)MM * DM];      // x fp16
__device__ __half  g_xgb [(size_t)MM * DM];      // xg fp16
__device__ __half  g_wb  [DM * DM];              // W_gate fp16
__device__ __half  g_wall[64 * DM];              // Wd|Wb|Wc|pad fp16 (64 rows)
__device__ __half  g_prm [3 * DM];               // bg|lnw|lnb fp16
__device__ float   g_abc [(size_t)MM * 48];      // A_bar|Bt|Ct
__device__ float   g_s   [(size_t)MM * DS];      // Ct*h
__device__ int     g_prog[BB];                   // scan progress (chunks done)

// ----------------------------- helpers -------------------------------------
__device__ __forceinline__ uint32_t smem_u32(const void* p) {
    uint32_t a;
    asm("{ .reg .u64 t; cvta.to.shared.u64 t, %1; cvt.u32.u64 %0, t; }"
        : "=r"(a) : "l"(p));
    return a;
}
__device__ __forceinline__ void cp16(uint32_t dst, const void* src) {
    asm volatile("cp.async.cg.shared.global [%0], [%1], 16;" :: "r"(dst), "l"(src));
}
#define CP_COMMIT() asm volatile("cp.async.commit_group;" ::: "memory")
#define CP_WAIT(n)  asm volatile("cp.async.wait_group %0;" :: "n"(n) : "memory")
#define SWZ(o) ((o) ^ (((o) >> 3) & 0x70))

#define LDSM_X4(r, a) \
    asm volatile("ldmatrix.sync.aligned.m8n8.x4.shared.b16 {%0,%1,%2,%3}, [%4];" \
        : "=r"((r)[0]), "=r"((r)[1]), "=r"((r)[2]), "=r"((r)[3]) : "r"(a))

__device__ __forceinline__ void mma16816(float* c, const uint32_t* a,
                                         uint32_t b0, uint32_t b1) {
    asm volatile(
        "mma.sync.aligned.m16n8k16.row.col.f32.f16.f16.f32 "
        "{%0,%1,%2,%3}, {%4,%5,%6,%7}, {%8,%9}, {%0,%1,%2,%3};"
        : "+f"(c[0]), "+f"(c[1]), "+f"(c[2]), "+f"(c[3])
        : "r"(a[0]), "r"(a[1]), "r"(a[2]), "r"(a[3]), "r"(b0), "r"(b1));
}

__device__ __forceinline__ float tanh_fast(float x) {
    float r; asm("tanh.approx.f32 %0, %1;" : "=f"(r) : "f"(x)); return r;
}
__device__ __forceinline__ float sigmoid_fast(float x) {
    return 1.0f / (1.0f + __expf(-x));
}
__device__ __forceinline__ float softplus_fast(float x) {
    if (x > 20.0f) return x;
    return __logf(1.0f + __expf(x));
}

// ---------------------------------------------------------------------------
// fused conversions (fp32 -> fp16). 4 contiguous-coalesced f4 per thread.
// blocks: [0,8192) x ; [8192,8448) W_gate ; [8448,8464) wall ; 8464 params+prog
// ---------------------------------------------------------------------------
__global__ void __launch_bounds__(256)
k_conv(const float4* __restrict__ xin, const float4* __restrict__ win,
       const float* __restrict__ Wd, const float* __restrict__ Wb,
       const float* __restrict__ Wc,
       const float* __restrict__ bg, const float* __restrict__ lnw,
       const float* __restrict__ lnb,
       __half2* __restrict__ xb, __half2* __restrict__ wb,
       __half2* __restrict__ wall, __half2* __restrict__ prm)
{
    const int blk = blockIdx.x, tid = threadIdx.x;
    if (blk < 8192) {
        const int base = blk * 1024 + tid;
#pragma unroll
        for (int k = 0; k < 4; k++) {
            const int i = base + k * 256;
            float4 v = xin[i];
            xb[i * 2]     = __floats2half2_rn(v.x, v.y);
            xb[i * 2 + 1] = __floats2half2_rn(v.z, v.w);
        }
    } else if (blk < 8448) {
        const int base = (blk - 8192) * 1024 + tid;
#pragma unroll
        for (int k = 0; k < 4; k++) {
            const int i = base + k * 256;
            float4 v = win[i];
            wb[i * 2]     = __floats2half2_rn(v.x, v.y);
            wb[i * 2 + 1] = __floats2half2_rn(v.z, v.w);
        }
    } else if (blk < 8464) {
        const int base = (blk - 8448) * 1024 + tid;
#pragma unroll
        for (int k = 0; k < 4; k++) {
            const int i = base + k * 256;       // 0..16383 (64 rows)
            const int row = i >> 8, k4 = i & 255;
            float4 v = make_float4(0.f, 0.f, 0.f, 0.f);
            if (row < 48) {
                const float* s = (row < 16) ? (Wd + (size_t)row * DM)
                               : (row < 32) ? (Wb + (size_t)(row - 16) * DM)
                                            : (Wc + (size_t)(row - 32) * DM);
                v = *(const float4*)(s + k4 * 4);
            }
            wall[i * 2]     = __floats2half2_rn(v.x, v.y);
            wall[i * 2 + 1] = __floats2half2_rn(v.z, v.w);
        }
    } else {
#pragma unroll
        for (int k = 0; k < 3; k++) {
            const int i = k * 256 + tid;        // 0..767 float4 slots
            const float* s = (i < 256) ? bg : (i < 512) ? lnw : lnb;
            float4 v = *(const float4*)(s + (i & 255) * 4);
            prm[i * 2]     = __floats2half2_rn(v.x, v.y);
            prm[i * 2 + 1] = __floats2half2_rn(v.z, v.w);
        }
        if (tid < BB) g_prog[tid] = 0;          // reset scan progress
    }
}

// ---------------------------------------------------------------------------
// fp16 mma.sync GEMM (3-stage, 2 CTAs/SM). NB = B rows per tile (128 or 64).
// NB=128: 2x4 warp grid, 64x32 warp tiles (EPI 0: gate -> fp16 Ch).
// NB=64 : 4x2 warp grid, 32x32 warp tiles (EPI 1: abc transform, cols<48).
// ---------------------------------------------------------------------------
#define NK 16

template<int NB, int EPI>
__global__ void __launch_bounds__(256, 2)
k_gemm(const __half* __restrict__ A, const __half* __restrict__ Bw,
       const float* __restrict__ Adiag, __half* __restrict__ Ch,
       float* __restrict__ Cf)
{
    constexpr int STG = 16384 + NB * 128;       // A(16KB) + B(NB*128B)
    constexpr int MI  = (NB == 128) ? 4 : 2;    // 16-row blocks per warp
    constexpr int WMR = MI * 16;                // warp m rows
    extern __shared__ char sraw[];
    const uint32_t sb = (smem_u32(sraw) + 1023u) & ~1023u;
    const int tid = threadIdx.x, wid = tid >> 5, lane = tid & 31;
    const int wm = (NB == 128) ? (wid >> 2) : (wid >> 1);
    const int wn = (NB == 128) ? (wid & 3)  : (wid & 1);
    const int n0 = blockIdx.x * 128, m0 = blockIdx.y * 128;

    const int rr = tid >> 3, cc = tid & 7;
    const __half* ag = A  + (size_t)(m0 + rr) * DM + cc * 8;
    const __half* bg = Bw + (size_t)(n0 + rr) * DM + cc * 8;

    auto load_stage = [&](int slot, int k) {
        const uint32_t ab = sb + slot * STG;
        const __half* a = ag + k * 64;
#pragma unroll
        for (int i = 0; i < 4; i++) {
            uint32_t off = (uint32_t)((rr + i * 32) * 128 + cc * 16);
            cp16(ab + SWZ(off), a + (size_t)i * 32 * DM);
        }
        const uint32_t bb2 = ab + 16384;
        const __half* b = bg + k * 64;
#pragma unroll
        for (int i = 0; i < NB / 32; i++) {
            uint32_t off = (uint32_t)((rr + i * 32) * 128 + cc * 16);
            cp16(bb2 + SWZ(off), b + (size_t)i * 32 * DM);
        }
        CP_COMMIT();
    };

    load_stage(0, 0); load_stage(1, 1); load_stage(2, 2);

    float acc[MI][4][4];
#pragma unroll
    for (int i = 0; i < MI; i++)
#pragma unroll
        for (int j = 0; j < 4; j++)
#pragma unroll
            for (int q = 0; q < 4; q++) acc[i][j][q] = 0.f;

    const int a_row = wm * WMR + ((lane >> 3) & 1) * 8 + (lane & 7);
    const int a_cb  = (lane >> 4) << 4;
    const int b_row = wn * 32 + ((lane >> 4) << 3) + (lane & 7);
    const int b_cb  = ((lane >> 3) & 1) << 4;

    for (int k = 0; k < NK; k++) {
        const int cur = k % 3;
        if (k <= NK - 3) CP_WAIT(2); else if (k == NK - 2) CP_WAIT(1); else CP_WAIT(0);
        __syncthreads();

        const uint32_t ab  = sb + cur * STG;
        const uint32_t bb2 = ab + 16384;
#pragma unroll
        for (int kk = 0; kk < 4; kk++) {
            const int kb = kk * 32;
            uint32_t af[MI][4], bf[2][4];
#pragma unroll
            for (int mi = 0; mi < MI; mi++) {
                uint32_t off = (uint32_t)((a_row + mi * 16) * 128 + kb + a_cb);
                LDSM_X4(af[mi], ab + SWZ(off));
            }
#pragma unroll
            for (int nj = 0; nj < 2; nj++) {
                uint32_t off = (uint32_t)((b_row + nj * 16) * 128 + kb + b_cb);
                LDSM_X4(bf[nj], bb2 + SWZ(off));
            }
#pragma unroll
            for (int mi = 0; mi < MI; mi++)
#pragma unroll
                for (int nj = 0; nj < 2; nj++) {
                    mma16816(acc[mi][2 * nj],     af[mi], bf[nj][0], bf[nj][1]);
                    mma16816(acc[mi][2 * nj + 1], af[mi], bf[nj][2], bf[nj][3]);
                }
        }
        __syncthreads();
        if (k + 3 < NK) load_stage(cur, k + 3);
    }

    const int g = lane >> 2, t2 = (lane & 3) * 2;
    if (EPI == 0) {
#pragma unroll
        for (int mi = 0; mi < MI; mi++) {
            const int row = m0 + wm * WMR + mi * 16 + g;
#pragma unroll
            for (int ni = 0; ni < 4; ni++) {
                const int col = n0 + wn * 32 + ni * 8 + t2;
                *(__half2*)(Ch + (size_t)row * DM + col) =
                    __floats2half2_rn(acc[mi][ni][0], acc[mi][ni][1]);
                *(__half2*)(Ch + (size_t)(row + 8) * DM + col) =
                    __floats2half2_rn(acc[mi][ni][2], acc[mi][ni][3]);
            }
        }
    } else {
#pragma unroll
        for (int mi = 0; mi < MI; mi++) {
            const int row = m0 + wm * WMR + mi * 16 + g;
#pragma unroll
            for (int ni = 0; ni < 4; ni++) {
                const int col = wn * 32 + ni * 8 + t2;
                if (col < 48) {
                    float v0 = acc[mi][ni][0], v1 = acc[mi][ni][1];
                    float v2 = acc[mi][ni][2], v3 = acc[mi][ni][3];
                    if (col < 16) {
                        const float a0 = __ldg(Adiag + col), a1 = __ldg(Adiag + col + 1);
                        v0 = __expf(softplus_fast(v0) * a0);
                        v1 = __expf(softplus_fast(v1) * a1);
                        v2 = __expf(softplus_fast(v2) * a0);
                        v3 = __expf(softplus_fast(v3) * a1);
                    }
                    float* p0 = Cf + (size_t)row * 48 + col;
                    float* p1 = Cf + (size_t)(row + 8) * 48 + col;
                    p0[0] = v0; p0[1] = v1;
                    p1[0] = v2; p1[1] = v3;
                }
            }
        }
    }
}

// ---------------------------------------------------------------------------
// LN(+bias) + sigmoid gate, xg = gate*x. Warp per token, 16-byte loads.
// ---------------------------------------------------------------------------
__global__ void __launch_bounds__(256)
k_lnxg(const __half* __restrict__ gph, const __half* __restrict__ xb,
       const __half* __restrict__ prm, __half* __restrict__ xgb)
{
    const int lane = threadIdx.x & 31;
    const int t = blockIdx.x * 8 + (threadIdx.x >> 5);
    const size_t base = (size_t)t * DM;

    float v[4][8];
    float s1 = 0.f, s2 = 0.f;
#pragma unroll
    for (int i = 0; i < 4; i++) {
        const int f8 = i * 256 + lane * 8;
        uint4 gv = *(const uint4*)(gph + base + f8);
        uint4 bv = *(const uint4*)(prm + f8);
        const __half2* gh = (const __half2*)&gv;
        const __half2* bh = (const __half2*)&bv;
#pragma unroll
        for (int q = 0; q < 4; q++) {
            float2 gg = __half22float2(gh[q]);
            float2 bb = __half22float2(bh[q]);
            float a0 = gg.x + bb.x, a1 = gg.y + bb.y;
            v[i][2 * q] = a0; v[i][2 * q + 1] = a1;
            s1 += a0 + a1;
            s2 += a0 * a0 + a1 * a1;
        }
    }
#pragma unroll
    for (int off = 16; off; off >>= 1) {
        s1 += __shfl_xor_sync(0xffffffffu, s1, off);
        s2 += __shfl_xor_sync(0xffffffffu, s2, off);
    }
    const float mean = s1 * (1.0f / DM);
    const float rstd = rsqrtf(s2 * (1.0f / DM) - mean * mean + LN_EPS);

#pragma unroll
    for (int i = 0; i < 4; i++) {
        const int f8 = i * 256 + lane * 8;
        uint4 xv = *(const uint4*)(xb + base + f8);
        uint4 wv = *(const uint4*)(prm + DM + f8);
        uint4 lv = *(const uint4*)(prm + 2 * DM + f8);
        const __half2* xh = (const __half2*)&xv;
        const __half2* wh = (const __half2*)&wv;
        const __half2* lh = (const __half2*)&lv;
        uint4 ov;
        __half2* oh = (__half2*)&ov;
#pragma unroll
        for (int q = 0; q < 4; q++) {
            float2 xx = __half22float2(xh[q]);
            float2 ww = __half22float2(wh[q]);
            float2 ll = __half22float2(lh[q]);
            float g0 = xx.x * sigmoid_fast((v[i][2*q]   - mean) * rstd * ww.x + ll.x);
            float g1 = xx.y * sigmoid_fast((v[i][2*q+1] - mean) * rstd * ww.y + ll.y);
            oh[q] = __floats2half2_rn(g0, g1);
        }
        *(uint4*)(xgb + base + f8) = ov;
    }
}

// ---------------------------------------------------------------------------
// FUSED scan + output, v3: CH=64 (smem ~25KB -> ~9 blocks/SM for out phase).
// blockIdx < BB: scan (warp0 consumes w/ all-ones fast path, warps1-7 prefetch)
// blockIdx >= BB: chunk-major out-blocks; W_out/D/x prefetched before spin.
// ---------------------------------------------------------------------------
#define CH 64
#define NCH (TT / CH)

__global__ void __launch_bounds__(256)
k_scanout(const float* __restrict__ abc, const float* __restrict__ mask,
          const float* __restrict__ h0, const float* __restrict__ Wout,
          const float* __restrict__ Dv, const __half* __restrict__ xb,
          float* __restrict__ sout, float* __restrict__ out, int out_size)
{
    __shared__ float sbuf[2][CH * 48];
    __shared__ float smask[2][CH];

    if (blockIdx.x < BB) {
        // ------------------------------ scan ------------------------------
        const int b = blockIdx.x, tid = threadIdx.x;
        const int lane = tid & 31, warp = tid >> 5;
        const float* abc_b  = abc  + (size_t)b * TT * 48;
        const float* mask_b = mask + (size_t)b * TT;
        {
            const float4* src = (const float4*)abc_b;
            float4* dst = (float4*)sbuf[0];
            for (int i = tid; i < CH * 48 / 4; i += 256) dst[i] = src[i];
            const float4* ms = (const float4*)mask_b;
            float4* md = (float4*)smask[0];
            for (int i = tid; i < CH / 4; i += 256) md[i] = ms[i];
        }
        __syncthreads();
        float h = 0.0f;
        if (warp == 0 && lane < DS) h = h0[b * DS + lane];
        for (int c = 0; c < NCH; c++) {
            const int cur = c & 1;
            if (warp > 0 && c + 1 < NCH) {
                const int tix = tid - 32;          // 0..223
                const float4* src = (const float4*)(abc_b + (size_t)(c + 1) * CH * 48);
                float4* dst = (float4*)sbuf[cur ^ 1];
                for (int i = tix; i < CH * 48 / 4; i += 224) dst[i] = src[i];
                const float4* ms = (const float4*)(mask_b + (size_t)(c + 1) * CH);
                float4* md = (float4*)smask[cur ^ 1];
                for (int i = tix; i < CH / 4; i += 224) md[i] = ms[i];
            }
            if (warp == 0) {
                const float* mk = smask[cur];
                float mm = fminf(mk[lane], mk[lane + 32]);
                const bool allone = __all_sync(0xffffffffu, mm == 1.0f);
                if (lane < DS) {
                    const float* buf = sbuf[cur];
                    float* sdst = sout + ((size_t)b * TT + (size_t)c * CH) * DS + lane;
                    if (allone) {
#pragma unroll 4
                        for (int t = 0; t < CH; t++) {
                            const float a  = buf[t * 48 + lane];
                            const float bb = buf[t * 48 + 16 + lane];
                            const float ct = buf[t * 48 + 32 + lane];
                            h = tanh_fast(fmaf(a, h, bb));
                            sdst[(size_t)t * DS] = ct * h;
                        }
                    } else {
#pragma unroll 4
                        for (int t = 0; t < CH; t++) {
                            const float a  = buf[t * 48 + lane];
                            const float bb = buf[t * 48 + 16 + lane];
                            const float ct = buf[t * 48 + 32 + lane];
                            const float m  = smask[cur][t];
                            const float hc = tanh_fast(fmaf(a, h, bb));
                            h = fmaf(m, hc, (1.0f - m) * h);
                            sdst[(size_t)t * DS] = ct * h;
                        }
                    }
                }
                __threadfence();                   // publish s stores
                __syncwarp();
                if (lane == 0) atomicAdd(&g_prog[b], 1);
            }
            __syncthreads();
        }
        if (warp == 0 && lane < DS && out_size >= MM * DM + BB * DS)
            out[(size_t)MM * DM + b * DS + lane] = h;
    } else {
        // ----------------------------- output -----------------------------
        float* s_s = sbuf[0];                      // reuse smem (256 floats)
        const int t = threadIdx.x;
        const int d = t * 4;
        const int j = blockIdx.x - BB;             // 0..2047, chunk-major
        const int chunk = j >> 5;                  // 0..63
        const int b     = (j >> 2) & 7;            // 0..7
        const int sub   = j & 3;                   // 0..3
        const int row0  = b * TT + chunk * CH + sub * 16;

        // prefetch everything that doesn't depend on the scan
        float4 wr[4][4];
#pragma unroll
        for (int r = 0; r < 4; r++)
#pragma unroll
            for (int q = 0; q < 4; q++)
                wr[r][q] = *(const float4*)(Wout + (size_t)(d + r) * DS + q * 4);
        const float4 dd = *(const float4*)(Dv + d);
        uint2 xu[16];
#pragma unroll
        for (int jj = 0; jj < 16; jj++)
            xu[jj] = *(const uint2*)(xb + (size_t)(row0 + jj) * DM + d);

        if (t == 0) {
            int p;
            do {
                asm volatile("ld.acquire.gpu.s32 %0, [%1];"
                             : "=r"(p) : "l"(g_prog + b) : "memory");
                if (p > chunk) break;
                __nanosleep(100);
            } while (true);
        }
        __syncthreads();

        if (t < 64)
            ((float4*)s_s)[t] = ((const float4*)(sout + (size_t)row0 * DS))[t];
        __syncthreads();

#pragma unroll 4
        for (int jj = 0; jj < 16; jj++) {
            const float4* sv = (const float4*)(s_s + jj * DS);
            const float4 s0 = sv[0], s1 = sv[1], s2 = sv[2], s3 = sv[3];
            float ys[4];
#pragma unroll
            for (int r = 0; r < 4; r++) {
                float a;
                a  = s0.x * wr[r][0].x + s0.y * wr[r][0].y + s0.z * wr[r][0].z + s0.w * wr[r][0].w;
                a += s1.x * wr[r][1].x + s1.y * wr[r][1].y + s1.z * wr[r][1].z + s1.w * wr[r][1].w;
                a += s2.x * wr[r][2].x + s2.y * wr[r][2].y + s2.z * wr[r][2].z + s2.w * wr[r][2].w;
                a += s3.x * wr[r][3].x + s3.y * wr[r][3].y + s3.z * wr[r][3].z + s3.w * wr[r][3].w;
                ys[r] = a;
            }
            const size_t base = (size_t)(row0 + jj) * DM + d;
            float2 x0 = __half22float2(*(__half2*)&xu[jj].x);
            float2 x1 = __half22float2(*(__half2*)&xu[jj].y);
            *(float4*)(out + base) = make_float4(ys[0] + dd.x * x0.x, ys[1] + dd.y * x0.y,
                                                 ys[2] + dd.z * x1.x, ys[3] + dd.w * x1.y);
        }
    }
}

// ---------------------------------------------------------------------------
extern "C" void kernel_launch(void* const* d_in, const int* in_sizes, int n_in,
                              void* d_out, int out_size)
{
    const float* x      = (const float*)d_in[0];
    const float* h0     = (const float*)d_in[1];
    const float* mask   = (const float*)d_in[2];
    const float* A_diag = (const float*)d_in[3];
    const float* W_del  = (const float*)d_in[4];
    const float* W_B    = (const float*)d_in[5];
    const float* W_C    = (const float*)d_in[6];
    const float* W_out  = (const float*)d_in[7];
    const float* Dv     = (const float*)d_in[8];
    const float* W_gate = (const float*)d_in[9];
    const float* b_gate = (const float*)d_in[10];
    const float* ln_w   = (const float*)d_in[11];
    const float* ln_b   = (const float*)d_in[12];
    float* out = (float*)d_out;

    float *abc, *sg;
    __half *gph, *xb, *xgb, *wb, *wall, *prm;
    cudaGetSymbolAddress((void**)&gph,  g_gph);
    cudaGetSymbolAddress((void**)&abc,  g_abc);
    cudaGetSymbolAddress((void**)&sg,   g_s);
    cudaGetSymbolAddress((void**)&xb,   g_xb);
    cudaGetSymbolAddress((void**)&xgb,  g_xgb);
    cudaGetSymbolAddress((void**)&wb,   g_wb);
    cudaGetSymbolAddress((void**)&wall, g_wall);
    cudaGetSymbolAddress((void**)&prm,  g_prm);

    const int smem_gate = 3 * (16384 + 128 * 128) + 1024;   // 99328
    const int smem_abc  = 3 * (16384 + 64 * 128)  + 1024;   // 74752
    cudaFuncSetAttribute(k_gemm<128, 0>, cudaFuncAttributeMaxDynamicSharedMemorySize, smem_gate);
    cudaFuncSetAttribute(k_gemm<64, 1>,  cudaFuncAttributeMaxDynamicSharedMemorySize, smem_abc);

    k_conv<<<8465, 256>>>((const float4*)x, (const float4*)W_gate,
                          W_del, W_B, W_C, b_gate, ln_w, ln_b,
                          (__half2*)xb, (__half2*)wb,
                          (__half2*)wall, (__half2*)prm);

    dim3 gg(DM / 128, MM / 128);
    k_gemm<128, 0><<<gg, 256, smem_gate>>>(xb, wb, nullptr, gph, nullptr);

    k_lnxg<<<MM / 8, 256>>>(gph, xb, prm, xgb);

    dim3 ga(1, MM / 128);
    k_gemm<64, 1><<<ga, 256, smem_abc>>>(xgb, wall, A_diag, nullptr, abc);

    k_scanout<<<BB + MM / 16, 256>>>(abc, mask, h0, W_out, Dv, xb,
                                     sg, out, out_size);
}

// round 16
// speedup vs baseline: 1.0595x; 1.0595x over previous
#include <cuda_runtime.h>
#include <cuda_fp16.h>
#include <cstdint>

#define BB     8
#define TT     4096
#define DM     1024
#define DS     16
#define MM     (BB * TT)
#define LN_EPS 1e-5f

// ------------------------- scratch (static, no alloc) ----------------------
__device__ __half  g_gph [(size_t)MM * DM];      // gate_pre fp16 (64 MB)
__device__ __half  g_xb  [(size_t)MM * DM];      // x fp16
__device__ __half  g_xgb [(size_t)MM * DM];      // xg fp16
__device__ __half  g_wb  [DM * DM];              // W_gate fp16
__device__ __half  g_wall[64 * DM];              // Wd|Wb|Wc|pad fp16 (64 rows)
__device__ __half  g_prm [3 * DM];               // bg|lnw|lnb fp16
__device__ float   g_abc [(size_t)MM * 48];      // A_bar|Bt|Ct
__device__ float   g_s   [(size_t)MM * DS];      // Ct*h
__device__ int     g_prog[BB];                   // scan progress (chunks done)

// ----------------------------- helpers -------------------------------------
__device__ __forceinline__ uint32_t smem_u32(const void* p) {
    uint32_t a;
    asm("{ .reg .u64 t; cvta.to.shared.u64 t, %1; cvt.u32.u64 %0, t; }"
        : "=r"(a) : "l"(p));
    return a;
}
__device__ __forceinline__ void cp16(uint32_t dst, const void* src) {
    asm volatile("cp.async.cg.shared.global [%0], [%1], 16;" :: "r"(dst), "l"(src));
}
#define CP_COMMIT() asm volatile("cp.async.commit_group;" ::: "memory")
#define CP_WAIT(n)  asm volatile("cp.async.wait_group %0;" :: "n"(n) : "memory")
#define SWZ(o) ((o) ^ (((o) >> 3) & 0x70))

#define LDSM_X4(r, a) \
    asm volatile("ldmatrix.sync.aligned.m8n8.x4.shared.b16 {%0,%1,%2,%3}, [%4];" \
        : "=r"((r)[0]), "=r"((r)[1]), "=r"((r)[2]), "=r"((r)[3]) : "r"(a))

__device__ __forceinline__ void mma16816(float* c, const uint32_t* a,
                                         uint32_t b0, uint32_t b1) {
    asm volatile(
        "mma.sync.aligned.m16n8k16.row.col.f32.f16.f16.f32 "
        "{%0,%1,%2,%3}, {%4,%5,%6,%7}, {%8,%9}, {%0,%1,%2,%3};"
        : "+f"(c[0]), "+f"(c[1]), "+f"(c[2]), "+f"(c[3])
        : "r"(a[0]), "r"(a[1]), "r"(a[2]), "r"(a[3]), "r"(b0), "r"(b1));
}

__device__ __forceinline__ float tanh_fast(float x) {
    float r; asm("tanh.approx.f32 %0, %1;" : "=f"(r) : "f"(x)); return r;
}
__device__ __forceinline__ float sigmoid_fast(float x) {
    return 1.0f / (1.0f + __expf(-x));
}
__device__ __forceinline__ float softplus_fast(float x) {
    if (x > 20.0f) return x;
    return __logf(1.0f + __expf(x));
}

// ---------------------------------------------------------------------------
// fused conversions (fp32 -> fp16). 4 contiguous-coalesced f4 per thread.
// blocks: [0,8192) x ; [8192,8448) W_gate ; [8448,8464) wall ; 8464 params+prog
// ---------------------------------------------------------------------------
__global__ void __launch_bounds__(256)
k_conv(const float4* __restrict__ xin, const float4* __restrict__ win,
       const float* __restrict__ Wd, const float* __restrict__ Wb,
       const float* __restrict__ Wc,
       const float* __restrict__ bg, const float* __restrict__ lnw,
       const float* __restrict__ lnb,
       __half2* __restrict__ xb, __half2* __restrict__ wb,
       __half2* __restrict__ wall, __half2* __restrict__ prm)
{
    const int blk = blockIdx.x, tid = threadIdx.x;
    if (blk < 8192) {
        const int base = blk * 1024 + tid;
#pragma unroll
        for (int k = 0; k < 4; k++) {
            const int i = base + k * 256;
            float4 v = xin[i];
            xb[i * 2]     = __floats2half2_rn(v.x, v.y);
            xb[i * 2 + 1] = __floats2half2_rn(v.z, v.w);
        }
    } else if (blk < 8448) {
        const int base = (blk - 8192) * 1024 + tid;
#pragma unroll
        for (int k = 0; k < 4; k++) {
            const int i = base + k * 256;
            float4 v = win[i];
            wb[i * 2]     = __floats2half2_rn(v.x, v.y);
            wb[i * 2 + 1] = __floats2half2_rn(v.z, v.w);
        }
    } else if (blk < 8464) {
        const int base = (blk - 8448) * 1024 + tid;
#pragma unroll
        for (int k = 0; k < 4; k++) {
            const int i = base + k * 256;       // 0..16383 (64 rows)
            const int row = i >> 8, k4 = i & 255;
            float4 v = make_float4(0.f, 0.f, 0.f, 0.f);
            if (row < 48) {
                const float* s = (row < 16) ? (Wd + (size_t)row * DM)
                               : (row < 32) ? (Wb + (size_t)(row - 16) * DM)
                                            : (Wc + (size_t)(row - 32) * DM);
                v = *(const float4*)(s + k4 * 4);
            }
            wall[i * 2]     = __floats2half2_rn(v.x, v.y);
            wall[i * 2 + 1] = __floats2half2_rn(v.z, v.w);
        }
    } else {
#pragma unroll
        for (int k = 0; k < 3; k++) {
            const int i = k * 256 + tid;        // 0..767 float4 slots
            const float* s = (i < 256) ? bg : (i < 512) ? lnw : lnb;
            float4 v = *(const float4*)(s + (i & 255) * 4);
            prm[i * 2]     = __floats2half2_rn(v.x, v.y);
            prm[i * 2 + 1] = __floats2half2_rn(v.z, v.w);
        }
        if (tid < BB) g_prog[tid] = 0;          // reset scan progress
    }
}

// ---------------------------------------------------------------------------
// fp16 mma.sync GEMM (3-stage, 2 CTAs/SM). NB = B rows per tile (128 or 64).
// NB=128: 2x4 warp grid, 64x32 warp tiles (EPI 0: gate -> fp16 Ch).
// NB=64 : 4x2 warp grid, 32x32 warp tiles (EPI 1: abc transform, cols<48).
// ---------------------------------------------------------------------------
#define NK 16

template<int NB, int EPI>
__global__ void __launch_bounds__(256, 2)
k_gemm(const __half* __restrict__ A, const __half* __restrict__ Bw,
       const float* __restrict__ Adiag, __half* __restrict__ Ch,
       float* __restrict__ Cf)
{
    constexpr int STG = 16384 + NB * 128;       // A(16KB) + B(NB*128B)
    constexpr int MI  = (NB == 128) ? 4 : 2;    // 16-row blocks per warp
    constexpr int WMR = MI * 16;                // warp m rows
    extern __shared__ char sraw[];
    const uint32_t sb = (smem_u32(sraw) + 1023u) & ~1023u;
    const int tid = threadIdx.x, wid = tid >> 5, lane = tid & 31;
    const int wm = (NB == 128) ? (wid >> 2) : (wid >> 1);
    const int wn = (NB == 128) ? (wid & 3)  : (wid & 1);
    const int n0 = blockIdx.x * 128, m0 = blockIdx.y * 128;

    const int rr = tid >> 3, cc = tid & 7;
    const __half* ag = A  + (size_t)(m0 + rr) * DM + cc * 8;
    const __half* bg = Bw + (size_t)(n0 + rr) * DM + cc * 8;

    auto load_stage = [&](int slot, int k) {
        const uint32_t ab = sb + slot * STG;
        const __half* a = ag + k * 64;
#pragma unroll
        for (int i = 0; i < 4; i++) {
            uint32_t off = (uint32_t)((rr + i * 32) * 128 + cc * 16);
            cp16(ab + SWZ(off), a + (size_t)i * 32 * DM);
        }
        const uint32_t bb2 = ab + 16384;
        const __half* b = bg + k * 64;
#pragma unroll
        for (int i = 0; i < NB / 32; i++) {
            uint32_t off = (uint32_t)((rr + i * 32) * 128 + cc * 16);
            cp16(bb2 + SWZ(off), b + (size_t)i * 32 * DM);
        }
        CP_COMMIT();
    };

    load_stage(0, 0); load_stage(1, 1); load_stage(2, 2);

    float acc[MI][4][4];
#pragma unroll
    for (int i = 0; i < MI; i++)
#pragma unroll
        for (int j = 0; j < 4; j++)
#pragma unroll
            for (int q = 0; q < 4; q++) acc[i][j][q] = 0.f;

    const int a_row = wm * WMR + ((lane >> 3) & 1) * 8 + (lane & 7);
    const int a_cb  = (lane >> 4) << 4;
    const int b_row = wn * 32 + ((lane >> 4) << 3) + (lane & 7);
    const int b_cb  = ((lane >> 3) & 1) << 4;

    for (int k = 0; k < NK; k++) {
        const int cur = k % 3;
        if (k <= NK - 3) CP_WAIT(2); else if (k == NK - 2) CP_WAIT(1); else CP_WAIT(0);
        __syncthreads();

        const uint32_t ab  = sb + cur * STG;
        const uint32_t bb2 = ab + 16384;
#pragma unroll
        for (int kk = 0; kk < 4; kk++) {
            const int kb = kk * 32;
            uint32_t af[MI][4], bf[2][4];
#pragma unroll
            for (int mi = 0; mi < MI; mi++) {
                uint32_t off = (uint32_t)((a_row + mi * 16) * 128 + kb + a_cb);
                LDSM_X4(af[mi], ab + SWZ(off));
            }
#pragma unroll
            for (int nj = 0; nj < 2; nj++) {
                uint32_t off = (uint32_t)((b_row + nj * 16) * 128 + kb + b_cb);
                LDSM_X4(bf[nj], bb2 + SWZ(off));
            }
#pragma unroll
            for (int mi = 0; mi < MI; mi++)
#pragma unroll
                for (int nj = 0; nj < 2; nj++) {
                    mma16816(acc[mi][2 * nj],     af[mi], bf[nj][0], bf[nj][1]);
                    mma16816(acc[mi][2 * nj + 1], af[mi], bf[nj][2], bf[nj][3]);
                }
        }
        __syncthreads();
        if (k + 3 < NK) load_stage(cur, k + 3);
    }

    const int g = lane >> 2, t2 = (lane & 3) * 2;
    if (EPI == 0) {
#pragma unroll
        for (int mi = 0; mi < MI; mi++) {
            const int row = m0 + wm * WMR + mi * 16 + g;
#pragma unroll
            for (int ni = 0; ni < 4; ni++) {
                const int col = n0 + wn * 32 + ni * 8 + t2;
                *(__half2*)(Ch + (size_t)row * DM + col) =
                    __floats2half2_rn(acc[mi][ni][0], acc[mi][ni][1]);
                *(__half2*)(Ch + (size_t)(row + 8) * DM + col) =
                    __floats2half2_rn(acc[mi][ni][2], acc[mi][ni][3]);
            }
        }
    } else {
#pragma unroll
        for (int mi = 0; mi < MI; mi++) {
            const int row = m0 + wm * WMR + mi * 16 + g;
#pragma unroll
            for (int ni = 0; ni < 4; ni++) {
                const int col = wn * 32 + ni * 8 + t2;
                if (col < 48) {
                    float v0 = acc[mi][ni][0], v1 = acc[mi][ni][1];
                    float v2 = acc[mi][ni][2], v3 = acc[mi][ni][3];
                    if (col < 16) {
                        const float a0 = __ldg(Adiag + col), a1 = __ldg(Adiag + col + 1);
                        v0 = __expf(softplus_fast(v0) * a0);
                        v1 = __expf(softplus_fast(v1) * a1);
                        v2 = __expf(softplus_fast(v2) * a0);
                        v3 = __expf(softplus_fast(v3) * a1);
                    }
                    float* p0 = Cf + (size_t)row * 48 + col;
                    float* p1 = Cf + (size_t)(row + 8) * 48 + col;
                    p0[0] = v0; p0[1] = v1;
                    p1[0] = v2; p1[1] = v3;
                }
            }
        }
    }
}

// ---------------------------------------------------------------------------
// LN(+bias) + sigmoid gate, xg = gate*x. Warp per token, 16-byte loads.
// ---------------------------------------------------------------------------
__global__ void __launch_bounds__(256)
k_lnxg(const __half* __restrict__ gph, const __half* __restrict__ xb,
       const __half* __restrict__ prm, __half* __restrict__ xgb)
{
    const int lane = threadIdx.x & 31;
    const int t = blockIdx.x * 8 + (threadIdx.x >> 5);
    const size_t base = (size_t)t * DM;

    float v[4][8];
    float s1 = 0.f, s2 = 0.f;
#pragma unroll
    for (int i = 0; i < 4; i++) {
        const int f8 = i * 256 + lane * 8;
        uint4 gv = *(const uint4*)(gph + base + f8);
        uint4 bv = *(const uint4*)(prm + f8);
        const __half2* gh = (const __half2*)&gv;
        const __half2* bh = (const __half2*)&bv;
#pragma unroll
        for (int q = 0; q < 4; q++) {
            float2 gg = __half22float2(gh[q]);
            float2 bb = __half22float2(bh[q]);
            float a0 = gg.x + bb.x, a1 = gg.y + bb.y;
            v[i][2 * q] = a0; v[i][2 * q + 1] = a1;
            s1 += a0 + a1;
            s2 += a0 * a0 + a1 * a1;
        }
    }
#pragma unroll
    for (int off = 16; off; off >>= 1) {
        s1 += __shfl_xor_sync(0xffffffffu, s1, off);
        s2 += __shfl_xor_sync(0xffffffffu, s2, off);
    }
    const float mean = s1 * (1.0f / DM);
    const float rstd = rsqrtf(s2 * (1.0f / DM) - mean * mean + LN_EPS);

#pragma unroll
    for (int i = 0; i < 4; i++) {
        const int f8 = i * 256 + lane * 8;
        uint4 xv = *(const uint4*)(xb + base + f8);
        uint4 wv = *(const uint4*)(prm + DM + f8);
        uint4 lv = *(const uint4*)(prm + 2 * DM + f8);
        const __half2* xh = (const __half2*)&xv;
        const __half2* wh = (const __half2*)&wv;
        const __half2* lh = (const __half2*)&lv;
        uint4 ov;
        __half2* oh = (__half2*)&ov;
#pragma unroll
        for (int q = 0; q < 4; q++) {
            float2 xx = __half22float2(xh[q]);
            float2 ww = __half22float2(wh[q]);
            float2 ll = __half22float2(lh[q]);
            float g0 = xx.x * sigmoid_fast((v[i][2*q]   - mean) * rstd * ww.x + ll.x);
            float g1 = xx.y * sigmoid_fast((v[i][2*q+1] - mean) * rstd * ww.y + ll.y);
            oh[q] = __floats2half2_rn(g0, g1);
        }
        *(uint4*)(xgb + base + f8) = ov;
    }
}

// ---------------------------------------------------------------------------
// FUSED scan + output (R14 config: CH=128).
// blockIdx < BB: scan (warp0 consumes w/ all-ones fast path, warps1-7 prefetch)
// blockIdx >= BB: chunk-major out-blocks; W_out/D/x prefetched before spin.
// ---------------------------------------------------------------------------
#define CH 128
#define NCH (TT / CH)

__global__ void __launch_bounds__(256)
k_scanout(const float* __restrict__ abc, const float* __restrict__ mask,
          const float* __restrict__ h0, const float* __restrict__ Wout,
          const float* __restrict__ Dv, const __half* __restrict__ xb,
          float* __restrict__ sout, float* __restrict__ out, int out_size)
{
    __shared__ float sbuf[2][CH * 48];
    __shared__ float smask[2][CH];

    if (blockIdx.x < BB) {
        // ------------------------------ scan ------------------------------
        const int b = blockIdx.x, tid = threadIdx.x;
        const int lane = tid & 31, warp = tid >> 5;
        const float* abc_b  = abc  + (size_t)b * TT * 48;
        const float* mask_b = mask + (size_t)b * TT;
        {
            const float4* src = (const float4*)abc_b;
            float4* dst = (float4*)sbuf[0];
            for (int i = tid; i < CH * 48 / 4; i += 256) dst[i] = src[i];
            const float4* ms = (const float4*)mask_b;
            float4* md = (float4*)smask[0];
            for (int i = tid; i < CH / 4; i += 256) md[i] = ms[i];
        }
        __syncthreads();
        float h = 0.0f;
        if (warp == 0 && lane < DS) h = h0[b * DS + lane];
        for (int c = 0; c < NCH; c++) {
            const int cur = c & 1;
            if (warp > 0 && c + 1 < NCH) {
                const int tix = tid - 32;          // 0..223
                const float4* src = (const float4*)(abc_b + (size_t)(c + 1) * CH * 48);
                float4* dst = (float4*)sbuf[cur ^ 1];
                for (int i = tix; i < CH * 48 / 4; i += 224) dst[i] = src[i];
                const float4* ms = (const float4*)(mask_b + (size_t)(c + 1) * CH);
                float4* md = (float4*)smask[cur ^ 1];
                for (int i = tix; i < CH / 4; i += 224) md[i] = ms[i];
            }
            if (warp == 0) {
                const float* mk = smask[cur];
                float mm = fminf(fminf(mk[lane * 4], mk[lane * 4 + 1]),
                                 fminf(mk[lane * 4 + 2], mk[lane * 4 + 3]));
                const bool allone = __all_sync(0xffffffffu, mm == 1.0f);
                if (lane < DS) {
                    const float* buf = sbuf[cur];
                    float* sdst = sout + ((size_t)b * TT + (size_t)c * CH) * DS + lane;
                    if (allone) {
#pragma unroll 4
                        for (int t = 0; t < CH; t++) {
                            const float a  = buf[t * 48 + lane];
                            const float bb = buf[t * 48 + 16 + lane];
                            const float ct = buf[t * 48 + 32 + lane];
                            h = tanh_fast(fmaf(a, h, bb));
                            sdst[(size_t)t * DS] = ct * h;
                        }
                    } else {
#pragma unroll 4
                        for (int t = 0; t < CH; t++) {
                            const float a  = buf[t * 48 + lane];
                            const float bb = buf[t * 48 + 16 + lane];
                            const float ct = buf[t * 48 + 32 + lane];
                            const float m  = smask[cur][t];
                            const float hc = tanh_fast(fmaf(a, h, bb));
                            h = fmaf(m, hc, (1.0f - m) * h);
                            sdst[(size_t)t * DS] = ct * h;
                        }
                    }
                }
                __threadfence();                   // publish s stores
                __syncwarp();
                if (lane == 0) atomicAdd(&g_prog[b], 1);
            }
            __syncthreads();
        }
        if (warp == 0 && lane < DS && out_size >= MM * DM + BB * DS)
            out[(size_t)MM * DM + b * DS + lane] = h;
    } else {
        // ----------------------------- output -----------------------------
        float* s_s = sbuf[0];                      // reuse smem (256 floats)
        const int t = threadIdx.x;
        const int d = t * 4;
        const int j = blockIdx.x - BB;             // 0..2047, chunk-major
        const int chunk = j >> 6;                  // 0..31
        const int b     = (j >> 3) & 7;            // 0..7
        const int sub   = j & 7;                   // 0..7
        const int row0  = b * TT + chunk * CH + sub * 16;

        // prefetch everything that doesn't depend on the scan
        float4 wr[4][4];
#pragma unroll
        for (int r = 0; r < 4; r++)
#pragma unroll
            for (int q = 0; q < 4; q++)
                wr[r][q] = *(const float4*)(Wout + (size_t)(d + r) * DS + q * 4);
        const float4 dd = *(const float4*)(Dv + d);
        uint2 xu[16];
#pragma unroll
        for (int jj = 0; jj < 16; jj++)
            xu[jj] = *(const uint2*)(xb + (size_t)(row0 + jj) * DM + d);

        if (t == 0) {
            int p;
            do {
                asm volatile("ld.acquire.gpu.s32 %0, [%1];"
                             : "=r"(p) : "l"(g_prog + b) : "memory");
                if (p > chunk) break;
                __nanosleep(100);
            } while (true);
        }
        __syncthreads();

        if (t < 64)
            ((float4*)s_s)[t] = ((const float4*)(sout + (size_t)row0 * DS))[t];
        __syncthreads();

#pragma unroll 4
        for (int jj = 0; jj < 16; jj++) {
            const float4* sv = (const float4*)(s_s + jj * DS);
            const float4 s0 = sv[0], s1 = sv[1], s2 = sv[2], s3 = sv[3];
            float ys[4];
#pragma unroll
            for (int r = 0; r < 4; r++) {
                float a;
                a  = s0.x * wr[r][0].x + s0.y * wr[r][0].y + s0.z * wr[r][0].z + s0.w * wr[r][0].w;
                a += s1.x * wr[r][1].x + s1.y * wr[r][1].y + s1.z * wr[r][1].z + s1.w * wr[r][1].w;
                a += s2.x * wr[r][2].x + s2.y * wr[r][2].y + s2.z * wr[r][2].z + s2.w * wr[r][2].w;
                a += s3.x * wr[r][3].x + s3.y * wr[r][3].y + s3.z * wr[r][3].z + s3.w * wr[r][3].w;
                ys[r] = a;
            }
            const size_t base = (size_t)(row0 + jj) * DM + d;
            float2 x0 = __half22float2(*(__half2*)&xu[jj].x);
            float2 x1 = __half22float2(*(__half2*)&xu[jj].y);
            *(float4*)(out + base) = make_float4(ys[0] + dd.x * x0.x, ys[1] + dd.y * x0.y,
                                                 ys[2] + dd.z * x1.x, ys[3] + dd.w * x1.y);
        }
    }
}

// ---------------------------------------------------------------------------
extern "C" void kernel_launch(void* const* d_in, const int* in_sizes, int n_in,
                              void* d_out, int out_size)
{
    const float* x      = (const float*)d_in[0];
    const float* h0     = (const float*)d_in[1];
    const float* mask   = (const float*)d_in[2];
    const float* A_diag = (const float*)d_in[3];
    const float* W_del  = (const float*)d_in[4];
    const float* W_B    = (const float*)d_in[5];
    const float* W_C    = (const float*)d_in[6];
    const float* W_out  = (const float*)d_in[7];
    const float* Dv     = (const float*)d_in[8];
    const float* W_gate = (const float*)d_in[9];
    const float* b_gate = (const float*)d_in[10];
    const float* ln_w   = (const float*)d_in[11];
    const float* ln_b   = (const float*)d_in[12];
    float* out = (float*)d_out;

    float *abc, *sg;
    __half *gph, *xb, *xgb, *wb, *wall, *prm;
    cudaGetSymbolAddress((void**)&gph,  g_gph);
    cudaGetSymbolAddress((void**)&abc,  g_abc);
    cudaGetSymbolAddress((void**)&sg,   g_s);
    cudaGetSymbolAddress((void**)&xb,   g_xb);
    cudaGetSymbolAddress((void**)&xgb,  g_xgb);
    cudaGetSymbolAddress((void**)&wb,   g_wb);
    cudaGetSymbolAddress((void**)&wall, g_wall);
    cudaGetSymbolAddress((void**)&prm,  g_prm);

    const int smem_gate = 3 * (16384 + 128 * 128) + 1024;   // 99328
    const int smem_abc  = 3 * (16384 + 64 * 128)  + 1024;   // 74752
    cudaFuncSetAttribute(k_gemm<128, 0>, cudaFuncAttributeMaxDynamicSharedMemorySize, smem_gate);
    cudaFuncSetAttribute(k_gemm<64, 1>,  cudaFuncAttributeMaxDynamicSharedMemorySize, smem_abc);

    k_conv<<<8465, 256>>>((const float4*)x, (const float4*)W_gate,
                          W_del, W_B, W_C, b_gate, ln_w, ln_b,
                          (__half2*)xb, (__half2*)wb,
                          (__half2*)wall, (__half2*)prm);

    dim3 gg(DM / 128, MM / 128);
    k_gemm<128, 0><<<gg, 256, smem_gate>>>(xb, wb, nullptr, gph, nullptr);

    k_lnxg<<<MM / 8, 256>>>(gph, xb, prm, xgb);

    dim3 ga(1, MM / 128);
    k_gemm<64, 1><<<ga, 256, smem_abc>>>(xgb, wall, A_diag, nullptr, abc);

    k_scanout<<<BB + MM / 16, 256>>>(abc, mask, h0, W_out, Dv, xb,
                                     sg, out, out_size);
}